// round 14
// baseline (speedup 1.0000x reference)
#include <cuda_runtime.h>
#include <cstdint>

// MoE gating, exact fp32, K-packed f32x2 GEMM. No khalf split: 8 warps x 16
// tokens, full K per warp; KC=128, 2-stage cp.async ring, 8 barriers total.
// x:[16384,1024] f32, gate_w:[64,1024] f32.
// out (f32): top_scores [T,2] | top_idx [T,2] | total_loss [1].

#define H      1024
#define NE     64
#define TM     128
#define NT     256
#define KC     128
#define NSTEP  8
#define RS     132                 // smem row stride (floats), 16B-aligned rows
#define WOFF   (128 * RS)          // 16896 floats
#define STG    (192 * RS)          // 25344 floats / stage
#define DSMEM  (2 * STG * 4)       // 202752 B
#define SPS    65
#define NBLK   128

__device__ float    g_pexp[NBLK * NE];
__device__ float    g_pz2[NBLK];
__device__ unsigned g_cnt = 0;

typedef unsigned long long ull;

__device__ __forceinline__ void fma2(ull& d, ull a, ull b) {
    asm("fma.rn.f32x2 %0, %1, %2, %0;" : "+l"(d) : "l"(a), "l"(b));
}
__device__ __forceinline__ uint32_t su32(const void* p) {
    uint32_t a;
    asm("{ .reg .u64 t; cvta.to.shared.u64 t, %1; cvt.u32.u64 %0, t; }"
        : "=r"(a) : "l"(p));
    return a;
}
__device__ __forceinline__ void cpa16(uint32_t dst, const float* src) {
    asm volatile("cp.async.cg.shared.global [%0], [%1], 16;" :: "r"(dst), "l"(src));
}

__global__ void __launch_bounds__(NT, 1) moe_gate(const float* __restrict__ x,
                                                  const float* __restrict__ w,
                                                  float* __restrict__ out,
                                                  int T) {
    extern __shared__ __align__(16) float dsm[];
    __shared__ float    s_red[8];
    __shared__ unsigned s_last;

    const int tid  = threadIdx.x;
    const int wid  = tid >> 5;
    const int lid  = tid & 31;
    const int tBlk = blockIdx.x * TM;
    const uint32_t sb = su32(dsm);

    // compute map: warp owns tokens {wid*16 + ty + 4i}, lanes: ty(4) x tx(8)
    const int tx = lid & 7;                // experts {tx + 8j}
    const int ty = lid >> 3;               // 0..3

    ull acc[4][8];
#pragma unroll
    for (int i = 0; i < 4; i++)
#pragma unroll
        for (int j = 0; j < 8; j++) acc[i][j] = 0ull;

#define STAGE(s_, slot_) do {                                                    \
    int _k0 = (s_) * KC;                                                         \
    uint32_t _sb = sb + (slot_) * (STG * 4);                                     \
    _Pragma("unroll")                                                            \
    for (int r = 0; r < 16; r++) {                                               \
        int idx = r * 256 + tid;                                                 \
        int row = idx >> 5, q = idx & 31;                                        \
        cpa16(_sb + (row * RS + 4 * q) * 4,                                      \
              x + (size_t)(tBlk + row) * H + _k0 + 4 * q);                       \
    }                                                                            \
    _Pragma("unroll")                                                            \
    for (int r = 0; r < 8; r++) {                                                \
        int idx = r * 256 + tid;                                                 \
        int row = idx >> 5, q = idx & 31;                                        \
        cpa16(_sb + (WOFF + row * RS + 4 * q) * 4,                               \
              w + (size_t)row * H + _k0 + 4 * q);                                \
    }                                                                            \
} while (0)

    // prologue
    STAGE(0, 0);
    asm volatile("cp.async.commit_group;" ::: "memory");

#pragma unroll 1
    for (int s = 0; s < NSTEP; s++) {
        asm volatile("cp.async.wait_group 0;" ::: "memory");
        __syncthreads();
        if (s + 1 < NSTEP) STAGE(s + 1, (s + 1) & 1);
        asm volatile("cp.async.commit_group;" ::: "memory");

        const float* xs = dsm + (s & 1) * STG + (wid * 16 + ty) * RS;
        const float* ws = dsm + (s & 1) * STG + WOFF + tx * RS;

        // 32 pair-blocks; each ulonglong2 = k-pairs (2blk*2, 2blk*2+1)
#pragma unroll 8
        for (int blk = 0; blk < 32; blk++) {
            ulonglong2 a[4], b[8];
#pragma unroll
            for (int i = 0; i < 4; i++)
                a[i] = *(const ulonglong2*)(xs + i * 4 * RS + 4 * blk);
#pragma unroll
            for (int j = 0; j < 8; j++)
                b[j] = *(const ulonglong2*)(ws + j * 8 * RS + 4 * blk);
#pragma unroll
            for (int i = 0; i < 4; i++)
#pragma unroll
                for (int j = 0; j < 8; j++)
                    fma2(acc[i][j], a[i].x, b[j].x);
#pragma unroll
            for (int i = 0; i < 4; i++)
#pragma unroll
                for (int j = 0; j < 8; j++)
                    fma2(acc[i][j], a[i].y, b[j].y);
        }
    }
    __syncthreads();

    // ---- logits -> sP[128][SPS] (single pass, no merge) ----
    float* sP    = dsm;
    float* sInv  = dsm + 128 * SPS;        // 128
    float* sLoad = sInv + 128;             // [4][64]
#pragma unroll
    for (int i = 0; i < 4; i++)
#pragma unroll
        for (int j = 0; j < 8; j++) {
            float2 f = *(float2*)&acc[i][j];
            sP[(wid * 16 + ty + 4 * i) * SPS + tx + 8 * j] = f.x + f.y;
        }
    __syncthreads();

    // ---- per-token softmax / top-2 ----
    float zsq = 0.0f;
    if (tid < TM) {
        float* row = sP + tid * SPS;
        float b1v = -1e30f, b2v = -1e30f;
        int   i1 = 0, i2 = 0;
#pragma unroll 8
        for (int e = 0; e < NE; e++) {
            float l = row[e];
            if (l > b1v)      { b2v = b1v; i2 = i1; b1v = l; i1 = e; }
            else if (l > b2v) { b2v = l;  i2 = e; }
        }
        float m = b1v, sum = 0.0f;
#pragma unroll 8
        for (int e = 0; e < NE; e++) {
            float ex = __expf(row[e] - m);
            sum += ex;
            row[e] = ex;
        }
        float inv = 1.0f / sum;
        sInv[tid] = inv;
        float z = m + __logf(sum);
        zsq = z * z;
        float p1 = __expf(b1v - m) * inv;
        float p2 = __expf(b2v - m) * inv;
        float dd = __expf(p2 - p1);
        int gt = tBlk + tid;
        out[2 * gt]             = 1.0f / (1.0f + dd);
        out[2 * gt + 1]         = dd / (1.0f + dd);
        out[2 * T + 2 * gt]     = (float)i1;
        out[2 * T + 2 * gt + 1] = (float)i2;
    }

    // ---- z-loss partial ----
#pragma unroll
    for (int off = 16; off > 0; off >>= 1)
        zsq += __shfl_down_sync(0xffffffffu, zsq, off);
    if (lid == 0) s_red[wid] = zsq;
    __syncthreads();
    if (tid == 0) {
        float s = 0.0f;
#pragma unroll
        for (int i = 0; i < 8; i++) s += s_red[i];
        g_pz2[blockIdx.x] = s;
    }

    // ---- expert-load partial, parallel over all 256 threads ----
    {
        int e = tid & 63, q = tid >> 6;
        float s = 0.0f;
#pragma unroll 8
        for (int t = 0; t < 32; t++) {
            int tok = q * 32 + t;
            s += sP[tok * SPS + e] * sInv[tok];
        }
        sLoad[q * 64 + e] = s;
    }
    __syncthreads();
    if (tid < NE)
        g_pexp[blockIdx.x * NE + tid] = sLoad[tid] + sLoad[64 + tid]
                                      + sLoad[128 + tid] + sLoad[192 + tid];

    // ---- fused finalize ----
    __threadfence();
    __syncthreads();
    if (tid == 0)
        s_last = (atomicAdd(&g_cnt, 1u) == (unsigned)(gridDim.x - 1)) ? 1u : 0u;
    __syncthreads();
    if (s_last) {
        __threadfence();
        int e = tid & 63, part = tid >> 6;
        float s = 0.0f;
#pragma unroll 4
        for (int b = part; b < NBLK; b += 4) s += g_pexp[b * NE + e];
        float z2 = (tid < NBLK) ? g_pz2[tid] : 0.0f;
        __syncthreads();
        float* redA = dsm;
        float* redZ = dsm + 256;
        redA[part * 64 + e] = s;
        redZ[tid] = z2;
        __syncthreads();
        if (tid < 64) {
            float load = (redA[tid] + redA[64 + tid] + redA[128 + tid] + redA[192 + tid]) / (float)T;
            float dv = load - 1.0f / 64.0f;
            float lb = dv * dv;
            float zz = redZ[tid] + redZ[tid + 64] + redZ[tid + 128] + redZ[tid + 192];
#pragma unroll
            for (int off = 16; off > 0; off >>= 1) {
                lb += __shfl_down_sync(0xffffffffu, lb, off);
                zz += __shfl_down_sync(0xffffffffu, zz, off);
            }
            if (lid == 0) { s_red[wid] = lb; s_red[4 + wid] = zz; }
        }
        __syncthreads();
        if (tid == 0) {
            out[4 * T] = 0.01f * 64.0f * (s_red[0] + s_red[1])
                       + 1e-4f * ((s_red[4] + s_red[5]) / (float)T);
            g_cnt = 0;
        }
    }
}

extern "C" void kernel_launch(void* const* d_in, const int* in_sizes, int n_in,
                              void* d_out, int out_size) {
    const float* x = (const float*)d_in[0];
    const float* w = (const float*)d_in[1];
    float* out = (float*)d_out;
    int T = in_sizes[0] / H;   // 16384
    cudaFuncSetAttribute(moe_gate, cudaFuncAttributeMaxDynamicSharedMemorySize, DSMEM);
    moe_gate<<<T / TM, NT, DSMEM>>>(x, w, out, T);   // grid = 128
}